// round 3
// baseline (speedup 1.0000x reference)
#include <cuda_runtime.h>
#include <math.h>

// Problem constants
// x: [B=2, R=16, C=512, E=1024], H=16 heads, D=64
// M = B*R*C = 16384, E = K = N = 1024
#define MTOT 16384
#define EDIM 1024
#define CDIM 512
#define HNUM 16
#define DDIM 64
#define NBH  512        // B*R*H

// Scratch: q/k/v/ctx in [bh][c][d] layout, 16384*1024 floats = 64MB each
__device__ float g_q[16777216];
__device__ float g_k[16777216];
__device__ float g_v[16777216];
__device__ float g_ctx[16777216];

// ---------------------------------------------------------------------------
// QKV projection: Y = X @ W + b, scattered into [bh][c][d] layout, optional scale
// Tiles: 128x128, BK=8, 256 threads, 8x8 per thread (4+4 split pattern)
// ---------------------------------------------------------------------------
__global__ __launch_bounds__(256) void qkv_proj_kernel(
    const float* __restrict__ A, const float* __restrict__ W,
    const float* __restrict__ bias, int which, float scale)
{
    __shared__ float As[8][132];   // transposed A tile, padded
    __shared__ float Bs[8][128];

    float* dst = (which == 0) ? g_q : (which == 1) ? g_k : g_v;

    const int m0 = blockIdx.y * 128;
    const int n0 = blockIdx.x * 128;
    const int t  = threadIdx.x;
    const int tx = t & 15, ty = t >> 4;
    const int arow = t >> 1, ac4 = (t & 1) * 4;
    const int brow = t >> 5, bc4 = (t & 31) * 4;

    float acc[8][8];
#pragma unroll
    for (int i = 0; i < 8; i++)
#pragma unroll
        for (int j = 0; j < 8; j++) acc[i][j] = 0.f;

    const float* Aptr = A + (size_t)(m0 + arow) * EDIM + ac4;
    const float* Wptr = W + (size_t)brow * EDIM + n0 + bc4;

    float4 av = *(const float4*)(Aptr);
    float4 bv = *(const float4*)(Wptr);

    for (int kt = 0; kt < EDIM; kt += 8) {
        As[ac4 + 0][arow] = av.x;
        As[ac4 + 1][arow] = av.y;
        As[ac4 + 2][arow] = av.z;
        As[ac4 + 3][arow] = av.w;
        *(float4*)&Bs[brow][bc4] = bv;
        __syncthreads();

        if (kt + 8 < EDIM) {
            av = *(const float4*)(Aptr + kt + 8);
            bv = *(const float4*)(Wptr + (size_t)(kt + 8) * EDIM);
        }

#pragma unroll
        for (int k = 0; k < 8; k++) {
            float a[8], b[8];
            float4 t0 = *(const float4*)&As[k][ty * 4];
            float4 t1 = *(const float4*)&As[k][64 + ty * 4];
            float4 t2 = *(const float4*)&Bs[k][tx * 4];
            float4 t3 = *(const float4*)&Bs[k][64 + tx * 4];
            a[0]=t0.x; a[1]=t0.y; a[2]=t0.z; a[3]=t0.w;
            a[4]=t1.x; a[5]=t1.y; a[6]=t1.z; a[7]=t1.w;
            b[0]=t2.x; b[1]=t2.y; b[2]=t2.z; b[3]=t2.w;
            b[4]=t3.x; b[5]=t3.y; b[6]=t3.z; b[7]=t3.w;
#pragma unroll
            for (int i = 0; i < 8; i++)
#pragma unroll
                for (int j = 0; j < 8; j++)
                    acc[i][j] += a[i] * b[j];
        }
        __syncthreads();
    }

    // Epilogue: scatter to [bh = (m/512)*16 + n/64][c = m%512][d = n%64]
#pragma unroll
    for (int i = 0; i < 8; i++) {
        int rr = (i < 4) ? (ty * 4 + i) : (64 + ty * 4 + i - 4);
        int m  = m0 + rr;
        int br = m >> 9;        // (b*R + r)
        int cp = m & 511;
#pragma unroll
        for (int j = 0; j < 8; j++) {
            int ccol = (j < 4) ? (tx * 4 + j) : (64 + tx * 4 + j - 4);
            int n = n0 + ccol;
            float v = (acc[i][j] + bias[n]) * scale;
            dst[((size_t)(br * HNUM + (n >> 6)) * CDIM + cp) * DDIM + (n & 63)] = v;
        }
    }
}

// ---------------------------------------------------------------------------
// Flash attention: one CTA per (bh, 64-row q block). 256 threads (16x16 grid),
// 4x4 microtile. Bc = 64, online softmax in fp32.
// ---------------------------------------------------------------------------
#define ATT_STRIDE 68
#define ATT_SMEM_FLOATS (4 * 64 * ATT_STRIDE)

__global__ __launch_bounds__(256) void attn_kernel()
{
    extern __shared__ float sm[];
    float* Qs = sm;                       // [64][68] transposed: Qs[d][qr]
    float* Ks = Qs + 64 * ATT_STRIDE;     // [64][68] transposed: Ks[d][kr]
    float* Vs = Ks + 64 * ATT_STRIDE;     // [64][68] natural:    Vs[kr][d]
    float* Ps = Vs + 64 * ATT_STRIDE;     // [64][68] transposed: Ps[kr][qr]

    const int blk = blockIdx.x;
    const int bh = blk >> 3, qb = blk & 7;
    const int t = threadIdx.x, tx = t & 15, ty = t >> 4;

    const float* qbase = g_q + (size_t)bh * (CDIM * DDIM) + qb * 64 * DDIM;
    const float* kbase = g_k + (size_t)bh * (CDIM * DDIM);
    const float* vbase = g_v + (size_t)bh * (CDIM * DDIM);

    // Load Q tile (transposed)
    for (int idx = t; idx < 4096; idx += 256) {
        int qr = idx >> 6, d = idx & 63;
        Qs[d * ATT_STRIDE + qr] = qbase[idx];
    }

    float m_i[4], l_i[4], o[4][4];
#pragma unroll
    for (int i = 0; i < 4; i++) {
        m_i[i] = -1e30f; l_i[i] = 0.f;
#pragma unroll
        for (int j = 0; j < 4; j++) o[i][j] = 0.f;
    }

    for (int kb = 0; kb < 8; kb++) {
        __syncthreads();  // protect Ks/Vs/Ps from previous iter's readers
        for (int idx = t; idx < 4096; idx += 256) {
            int kr = idx >> 6, d = idx & 63;
            Ks[d * ATT_STRIDE + kr] = kbase[kb * 4096 + idx];
            Vs[kr * ATT_STRIDE + d] = vbase[kb * 4096 + idx];
        }
        __syncthreads();

        // S = Q K^T  (Q already scaled by 1/8)
        float s[4][4];
#pragma unroll
        for (int i = 0; i < 4; i++)
#pragma unroll
            for (int j = 0; j < 4; j++) s[i][j] = 0.f;

#pragma unroll 4
        for (int d = 0; d < 64; d++) {
            float4 aq = *(const float4*)&Qs[d * ATT_STRIDE + ty * 4];
            float4 bk = *(const float4*)&Ks[d * ATT_STRIDE + tx * 4];
            float a[4] = {aq.x, aq.y, aq.z, aq.w};
            float b[4] = {bk.x, bk.y, bk.z, bk.w};
#pragma unroll
            for (int i = 0; i < 4; i++)
#pragma unroll
                for (int j = 0; j < 4; j++)
                    s[i][j] += a[i] * b[j];
        }

        // Online softmax update (rows = ty*4+i, reduce over the 16 tx lanes)
#pragma unroll
        for (int i = 0; i < 4; i++) {
            float rm = fmaxf(fmaxf(s[i][0], s[i][1]), fmaxf(s[i][2], s[i][3]));
#pragma unroll
            for (int off = 8; off > 0; off >>= 1)
                rm = fmaxf(rm, __shfl_xor_sync(0xffffffffu, rm, off));
            float mn = fmaxf(m_i[i], rm);
            float corr = __expf(m_i[i] - mn);
            m_i[i] = mn;
            float ps = 0.f;
#pragma unroll
            for (int j = 0; j < 4; j++) {
                s[i][j] = __expf(s[i][j] - mn);
                ps += s[i][j];
            }
#pragma unroll
            for (int off = 8; off > 0; off >>= 1)
                ps += __shfl_xor_sync(0xffffffffu, ps, off);
            l_i[i] = l_i[i] * corr + ps;
#pragma unroll
            for (int j = 0; j < 4; j++) o[i][j] *= corr;
        }

        // Write P (transposed) for the PV GEMM
#pragma unroll
        for (int i = 0; i < 4; i++)
#pragma unroll
            for (int j = 0; j < 4; j++)
                Ps[(tx * 4 + j) * ATT_STRIDE + ty * 4 + i] = s[i][j];
        __syncthreads();

        // O += P @ V
#pragma unroll 4
        for (int kr = 0; kr < 64; kr++) {
            float4 ap = *(const float4*)&Ps[kr * ATT_STRIDE + ty * 4];
            float4 bv = *(const float4*)&Vs[kr * ATT_STRIDE + tx * 4];
            float a[4] = {ap.x, ap.y, ap.z, ap.w};
            float b[4] = {bv.x, bv.y, bv.z, bv.w};
#pragma unroll
            for (int i = 0; i < 4; i++)
#pragma unroll
                for (int j = 0; j < 4; j++)
                    o[i][j] += a[i] * b[j];
        }
    }

    // Normalize and write ctx
    float* obase = g_ctx + (size_t)bh * (CDIM * DDIM) + qb * 64 * DDIM;
#pragma unroll
    for (int i = 0; i < 4; i++) {
        float inv = 1.f / l_i[i];
#pragma unroll
        for (int j = 0; j < 4; j++)
            obase[(ty * 4 + i) * DDIM + tx * 4 + j] = o[i][j] * inv;
    }
}

// ---------------------------------------------------------------------------
// Output projection: out = ctx @ Wo + bo, ctx gathered from [bh][c][d] layout
// ---------------------------------------------------------------------------
__global__ __launch_bounds__(256) void out_proj_kernel(
    const float* __restrict__ W, const float* __restrict__ bias,
    float* __restrict__ out)
{
    __shared__ float As[8][132];
    __shared__ float Bs[8][128];

    const int m0 = blockIdx.y * 128;
    const int n0 = blockIdx.x * 128;
    const int t  = threadIdx.x;
    const int tx = t & 15, ty = t >> 4;
    const int arow = t >> 1, ac4 = (t & 1) * 4;
    const int brow = t >> 5, bc4 = (t & 31) * 4;

    float acc[8][8];
#pragma unroll
    for (int i = 0; i < 8; i++)
#pragma unroll
        for (int j = 0; j < 8; j++) acc[i][j] = 0.f;

    // A gather precompute: m fixed per thread
    const int m  = m0 + arow;
    const int br = m >> 9;
    const int cp = m & 511;
    const float* Wptr = W + (size_t)brow * EDIM + n0 + bc4;

    // A element (m, k): g_ctx[(br*16 + k/64)*512*64 + cp*64 + k%64]
    auto aload = [&](int k) -> float4 {
        const float* src = g_ctx +
            ((size_t)(br * HNUM + (k >> 6)) * CDIM + cp) * DDIM + (k & 63);
        return *(const float4*)src;
    };

    float4 av = aload(ac4);
    float4 bv = *(const float4*)(Wptr);

    for (int kt = 0; kt < EDIM; kt += 8) {
        As[ac4 + 0][arow] = av.x;
        As[ac4 + 1][arow] = av.y;
        As[ac4 + 2][arow] = av.z;
        As[ac4 + 3][arow] = av.w;
        *(float4*)&Bs[brow][bc4] = bv;
        __syncthreads();

        if (kt + 8 < EDIM) {
            av = aload(kt + 8 + ac4);
            bv = *(const float4*)(Wptr + (size_t)(kt + 8) * EDIM);
        }

#pragma unroll
        for (int k = 0; k < 8; k++) {
            float a[8], b[8];
            float4 t0 = *(const float4*)&As[k][ty * 4];
            float4 t1 = *(const float4*)&As[k][64 + ty * 4];
            float4 t2 = *(const float4*)&Bs[k][tx * 4];
            float4 t3 = *(const float4*)&Bs[k][64 + tx * 4];
            a[0]=t0.x; a[1]=t0.y; a[2]=t0.z; a[3]=t0.w;
            a[4]=t1.x; a[5]=t1.y; a[6]=t1.z; a[7]=t1.w;
            b[0]=t2.x; b[1]=t2.y; b[2]=t2.z; b[3]=t2.w;
            b[4]=t3.x; b[5]=t3.y; b[6]=t3.z; b[7]=t3.w;
#pragma unroll
            for (int i = 0; i < 8; i++)
#pragma unroll
                for (int j = 0; j < 8; j++)
                    acc[i][j] += a[i] * b[j];
        }
        __syncthreads();
    }

#pragma unroll
    for (int i = 0; i < 8; i++) {
        int rr = (i < 4) ? (ty * 4 + i) : (64 + ty * 4 + i - 4);
        int mm = m0 + rr;
#pragma unroll
        for (int j = 0; j < 8; j++) {
            int ccol = (j < 4) ? (tx * 4 + j) : (64 + tx * 4 + j - 4);
            int n = n0 + ccol;
            out[(size_t)mm * EDIM + n] = acc[i][j] + bias[n];
        }
    }
}

// ---------------------------------------------------------------------------
extern "C" void kernel_launch(void* const* d_in, const int* in_sizes, int n_in,
                              void* d_out, int out_size)
{
    const float* x  = (const float*)d_in[0];
    const float* wq = (const float*)d_in[1];
    const float* bq = (const float*)d_in[2];
    const float* wk = (const float*)d_in[3];
    const float* bk = (const float*)d_in[4];
    const float* wv = (const float*)d_in[5];
    const float* bv = (const float*)d_in[6];
    const float* wo = (const float*)d_in[7];
    const float* bo = (const float*)d_in[8];
    float* out = (float*)d_out;

    dim3 pg(EDIM / 128, MTOT / 128);   // (8, 128)
    dim3 pb(256);

    // Q scaled by 1/sqrt(D) = 0.125 in the epilogue
    qkv_proj_kernel<<<pg, pb>>>(x, wq, bq, 0, 0.125f);
    qkv_proj_kernel<<<pg, pb>>>(x, wk, bk, 1, 1.0f);
    qkv_proj_kernel<<<pg, pb>>>(x, wv, bv, 2, 1.0f);

    const int smem_bytes = ATT_SMEM_FLOATS * (int)sizeof(float);  // 69632
    cudaFuncSetAttribute(attn_kernel,
                         cudaFuncAttributeMaxDynamicSharedMemorySize, smem_bytes);
    attn_kernel<<<NBH * 8, 256, smem_bytes>>>();

    out_proj_kernel<<<pg, pb>>>(wo, bo, out);
}

// round 4
// speedup vs baseline: 1.0007x; 1.0007x over previous
#include <cuda_runtime.h>
#include <math.h>

// Problem constants
// x: [B=2, R=16, C=512, E=1024], H=16 heads, D=64
// M = B*R*C = 16384, E = K = N = 1024
#define MTOT 16384
#define EDIM 1024
#define CDIM 512
#define HNUM 16
#define DDIM 64
#define NBH  512        // B*R*H

// Scratch: q/k/v/ctx in [bh][c][d] layout, 16384*1024 floats = 64MB each
__device__ float g_q[16777216];
__device__ float g_k[16777216];
__device__ float g_v[16777216];
__device__ float g_ctx[16777216];

// ---------------------------------------------------------------------------
// QKV projection: Y = X @ W + b, scattered into [bh][c][d] layout, optional scale
// Tiles: 128x128, BK=8, 256 threads, 8x8 per thread (4+4 split pattern)
// ---------------------------------------------------------------------------
__global__ __launch_bounds__(256) void qkv_proj_kernel(
    const float* __restrict__ A, const float* __restrict__ W,
    const float* __restrict__ bias, int which, float scale)
{
    __shared__ float As[8][132];   // transposed A tile, padded
    __shared__ float Bs[8][128];

    float* dst = (which == 0) ? g_q : (which == 1) ? g_k : g_v;

    const int m0 = blockIdx.y * 128;
    const int n0 = blockIdx.x * 128;
    const int t  = threadIdx.x;
    const int tx = t & 15, ty = t >> 4;
    const int arow = t >> 1, ac4 = (t & 1) * 4;
    const int brow = t >> 5, bc4 = (t & 31) * 4;

    float acc[8][8];
#pragma unroll
    for (int i = 0; i < 8; i++)
#pragma unroll
        for (int j = 0; j < 8; j++) acc[i][j] = 0.f;

    const float* Aptr = A + (size_t)(m0 + arow) * EDIM + ac4;
    const float* Wptr = W + (size_t)brow * EDIM + n0 + bc4;

    float4 av = *(const float4*)(Aptr);
    float4 bv = *(const float4*)(Wptr);

    for (int kt = 0; kt < EDIM; kt += 8) {
        As[ac4 + 0][arow] = av.x;
        As[ac4 + 1][arow] = av.y;
        As[ac4 + 2][arow] = av.z;
        As[ac4 + 3][arow] = av.w;
        *(float4*)&Bs[brow][bc4] = bv;
        __syncthreads();

        if (kt + 8 < EDIM) {
            av = *(const float4*)(Aptr + kt + 8);
            bv = *(const float4*)(Wptr + (size_t)(kt + 8) * EDIM);
        }

#pragma unroll
        for (int k = 0; k < 8; k++) {
            float a[8], b[8];
            float4 t0 = *(const float4*)&As[k][ty * 4];
            float4 t1 = *(const float4*)&As[k][64 + ty * 4];
            float4 t2 = *(const float4*)&Bs[k][tx * 4];
            float4 t3 = *(const float4*)&Bs[k][64 + tx * 4];
            a[0]=t0.x; a[1]=t0.y; a[2]=t0.z; a[3]=t0.w;
            a[4]=t1.x; a[5]=t1.y; a[6]=t1.z; a[7]=t1.w;
            b[0]=t2.x; b[1]=t2.y; b[2]=t2.z; b[3]=t2.w;
            b[4]=t3.x; b[5]=t3.y; b[6]=t3.z; b[7]=t3.w;
#pragma unroll
            for (int i = 0; i < 8; i++)
#pragma unroll
                for (int j = 0; j < 8; j++)
                    acc[i][j] += a[i] * b[j];
        }
        __syncthreads();
    }

    // Epilogue: scatter to [bh = (m/512)*16 + n/64][c = m%512][d = n%64]
#pragma unroll
    for (int i = 0; i < 8; i++) {
        int rr = (i < 4) ? (ty * 4 + i) : (64 + ty * 4 + i - 4);
        int m  = m0 + rr;
        int br = m >> 9;        // (b*R + r)
        int cp = m & 511;
#pragma unroll
        for (int j = 0; j < 8; j++) {
            int ccol = (j < 4) ? (tx * 4 + j) : (64 + tx * 4 + j - 4);
            int n = n0 + ccol;
            float v = (acc[i][j] + bias[n]) * scale;
            dst[((size_t)(br * HNUM + (n >> 6)) * CDIM + cp) * DDIM + (n & 63)] = v;
        }
    }
}

// ---------------------------------------------------------------------------
// Flash attention: one CTA per (bh, 64-row q block). 256 threads (16x16 grid),
// 4x4 microtile. Bc = 64, online softmax in fp32.
// ---------------------------------------------------------------------------
#define ATT_STRIDE 68
#define ATT_SMEM_FLOATS (4 * 64 * ATT_STRIDE)

__global__ __launch_bounds__(256) void attn_kernel()
{
    extern __shared__ float sm[];
    float* Qs = sm;                       // [64][68] transposed: Qs[d][qr]
    float* Ks = Qs + 64 * ATT_STRIDE;     // [64][68] transposed: Ks[d][kr]
    float* Vs = Ks + 64 * ATT_STRIDE;     // [64][68] natural:    Vs[kr][d]
    float* Ps = Vs + 64 * ATT_STRIDE;     // [64][68] transposed: Ps[kr][qr]

    const int blk = blockIdx.x;
    const int bh = blk >> 3, qb = blk & 7;
    const int t = threadIdx.x, tx = t & 15, ty = t >> 4;

    const float* qbase = g_q + (size_t)bh * (CDIM * DDIM) + qb * 64 * DDIM;
    const float* kbase = g_k + (size_t)bh * (CDIM * DDIM);
    const float* vbase = g_v + (size_t)bh * (CDIM * DDIM);

    // Load Q tile (transposed)
    for (int idx = t; idx < 4096; idx += 256) {
        int qr = idx >> 6, d = idx & 63;
        Qs[d * ATT_STRIDE + qr] = qbase[idx];
    }

    float m_i[4], l_i[4], o[4][4];
#pragma unroll
    for (int i = 0; i < 4; i++) {
        m_i[i] = -1e30f; l_i[i] = 0.f;
#pragma unroll
        for (int j = 0; j < 4; j++) o[i][j] = 0.f;
    }

    for (int kb = 0; kb < 8; kb++) {
        __syncthreads();  // protect Ks/Vs/Ps from previous iter's readers
        for (int idx = t; idx < 4096; idx += 256) {
            int kr = idx >> 6, d = idx & 63;
            Ks[d * ATT_STRIDE + kr] = kbase[kb * 4096 + idx];
            Vs[kr * ATT_STRIDE + d] = vbase[kb * 4096 + idx];
        }
        __syncthreads();

        // S = Q K^T  (Q already scaled by 1/8)
        float s[4][4];
#pragma unroll
        for (int i = 0; i < 4; i++)
#pragma unroll
            for (int j = 0; j < 4; j++) s[i][j] = 0.f;

#pragma unroll 4
        for (int d = 0; d < 64; d++) {
            float4 aq = *(const float4*)&Qs[d * ATT_STRIDE + ty * 4];
            float4 bk = *(const float4*)&Ks[d * ATT_STRIDE + tx * 4];
            float a[4] = {aq.x, aq.y, aq.z, aq.w};
            float b[4] = {bk.x, bk.y, bk.z, bk.w};
#pragma unroll
            for (int i = 0; i < 4; i++)
#pragma unroll
                for (int j = 0; j < 4; j++)
                    s[i][j] += a[i] * b[j];
        }

        // Online softmax update (rows = ty*4+i, reduce over the 16 tx lanes)
#pragma unroll
        for (int i = 0; i < 4; i++) {
            float rm = fmaxf(fmaxf(s[i][0], s[i][1]), fmaxf(s[i][2], s[i][3]));
#pragma unroll
            for (int off = 8; off > 0; off >>= 1)
                rm = fmaxf(rm, __shfl_xor_sync(0xffffffffu, rm, off));
            float mn = fmaxf(m_i[i], rm);
            float corr = __expf(m_i[i] - mn);
            m_i[i] = mn;
            float ps = 0.f;
#pragma unroll
            for (int j = 0; j < 4; j++) {
                s[i][j] = __expf(s[i][j] - mn);
                ps += s[i][j];
            }
#pragma unroll
            for (int off = 8; off > 0; off >>= 1)
                ps += __shfl_xor_sync(0xffffffffu, ps, off);
            l_i[i] = l_i[i] * corr + ps;
#pragma unroll
            for (int j = 0; j < 4; j++) o[i][j] *= corr;
        }

        // Write P (transposed) for the PV GEMM
#pragma unroll
        for (int i = 0; i < 4; i++)
#pragma unroll
            for (int j = 0; j < 4; j++)
                Ps[(tx * 4 + j) * ATT_STRIDE + ty * 4 + i] = s[i][j];
        __syncthreads();

        // O += P @ V
#pragma unroll 4
        for (int kr = 0; kr < 64; kr++) {
            float4 ap = *(const float4*)&Ps[kr * ATT_STRIDE + ty * 4];
            float4 bv = *(const float4*)&Vs[kr * ATT_STRIDE + tx * 4];
            float a[4] = {ap.x, ap.y, ap.z, ap.w};
            float b[4] = {bv.x, bv.y, bv.z, bv.w};
#pragma unroll
            for (int i = 0; i < 4; i++)
#pragma unroll
                for (int j = 0; j < 4; j++)
                    o[i][j] += a[i] * b[j];
        }
    }

    // Normalize and write ctx
    float* obase = g_ctx + (size_t)bh * (CDIM * DDIM) + qb * 64 * DDIM;
#pragma unroll
    for (int i = 0; i < 4; i++) {
        float inv = 1.f / l_i[i];
#pragma unroll
        for (int j = 0; j < 4; j++)
            obase[(ty * 4 + i) * DDIM + tx * 4 + j] = o[i][j] * inv;
    }
}

// ---------------------------------------------------------------------------
// Output projection: out = ctx @ Wo + bo, ctx gathered from [bh][c][d] layout
// ---------------------------------------------------------------------------
__global__ __launch_bounds__(256) void out_proj_kernel(
    const float* __restrict__ W, const float* __restrict__ bias,
    float* __restrict__ out)
{
    __shared__ float As[8][132];
    __shared__ float Bs[8][128];

    const int m0 = blockIdx.y * 128;
    const int n0 = blockIdx.x * 128;
    const int t  = threadIdx.x;
    const int tx = t & 15, ty = t >> 4;
    const int arow = t >> 1, ac4 = (t & 1) * 4;
    const int brow = t >> 5, bc4 = (t & 31) * 4;

    float acc[8][8];
#pragma unroll
    for (int i = 0; i < 8; i++)
#pragma unroll
        for (int j = 0; j < 8; j++) acc[i][j] = 0.f;

    // A gather precompute: m fixed per thread
    const int m  = m0 + arow;
    const int br = m >> 9;
    const int cp = m & 511;
    const float* Wptr = W + (size_t)brow * EDIM + n0 + bc4;

    // A element (m, k): g_ctx[(br*16 + k/64)*512*64 + cp*64 + k%64]
    auto aload = [&](int k) -> float4 {
        const float* src = g_ctx +
            ((size_t)(br * HNUM + (k >> 6)) * CDIM + cp) * DDIM + (k & 63);
        return *(const float4*)src;
    };

    float4 av = aload(ac4);
    float4 bv = *(const float4*)(Wptr);

    for (int kt = 0; kt < EDIM; kt += 8) {
        As[ac4 + 0][arow] = av.x;
        As[ac4 + 1][arow] = av.y;
        As[ac4 + 2][arow] = av.z;
        As[ac4 + 3][arow] = av.w;
        *(float4*)&Bs[brow][bc4] = bv;
        __syncthreads();

        if (kt + 8 < EDIM) {
            av = aload(kt + 8 + ac4);
            bv = *(const float4*)(Wptr + (size_t)(kt + 8) * EDIM);
        }

#pragma unroll
        for (int k = 0; k < 8; k++) {
            float a[8], b[8];
            float4 t0 = *(const float4*)&As[k][ty * 4];
            float4 t1 = *(const float4*)&As[k][64 + ty * 4];
            float4 t2 = *(const float4*)&Bs[k][tx * 4];
            float4 t3 = *(const float4*)&Bs[k][64 + tx * 4];
            a[0]=t0.x; a[1]=t0.y; a[2]=t0.z; a[3]=t0.w;
            a[4]=t1.x; a[5]=t1.y; a[6]=t1.z; a[7]=t1.w;
            b[0]=t2.x; b[1]=t2.y; b[2]=t2.z; b[3]=t2.w;
            b[4]=t3.x; b[5]=t3.y; b[6]=t3.z; b[7]=t3.w;
#pragma unroll
            for (int i = 0; i < 8; i++)
#pragma unroll
                for (int j = 0; j < 8; j++)
                    acc[i][j] += a[i] * b[j];
        }
        __syncthreads();
    }

#pragma unroll
    for (int i = 0; i < 8; i++) {
        int rr = (i < 4) ? (ty * 4 + i) : (64 + ty * 4 + i - 4);
        int mm = m0 + rr;
#pragma unroll
        for (int j = 0; j < 8; j++) {
            int ccol = (j < 4) ? (tx * 4 + j) : (64 + tx * 4 + j - 4);
            int n = n0 + ccol;
            out[(size_t)mm * EDIM + n] = acc[i][j] + bias[n];
        }
    }
}

// ---------------------------------------------------------------------------
extern "C" void kernel_launch(void* const* d_in, const int* in_sizes, int n_in,
                              void* d_out, int out_size)
{
    const float* x  = (const float*)d_in[0];
    const float* wq = (const float*)d_in[1];
    const float* bq = (const float*)d_in[2];
    const float* wk = (const float*)d_in[3];
    const float* bk = (const float*)d_in[4];
    const float* wv = (const float*)d_in[5];
    const float* bv = (const float*)d_in[6];
    const float* wo = (const float*)d_in[7];
    const float* bo = (const float*)d_in[8];
    float* out = (float*)d_out;

    dim3 pg(EDIM / 128, MTOT / 128);   // (8, 128)
    dim3 pb(256);

    // Q scaled by 1/sqrt(D) = 0.125 in the epilogue
    qkv_proj_kernel<<<pg, pb>>>(x, wq, bq, 0, 0.125f);
    qkv_proj_kernel<<<pg, pb>>>(x, wk, bk, 1, 1.0f);
    qkv_proj_kernel<<<pg, pb>>>(x, wv, bv, 2, 1.0f);

    const int smem_bytes = ATT_SMEM_FLOATS * (int)sizeof(float);  // 69632
    cudaFuncSetAttribute(attn_kernel,
                         cudaFuncAttributeMaxDynamicSharedMemorySize, smem_bytes);
    attn_kernel<<<NBH * 8, 256, smem_bytes>>>();

    out_proj_kernel<<<pg, pb>>>(wo, bo, out);
}

// round 6
// speedup vs baseline: 1.2438x; 1.2428x over previous
#include <cuda_runtime.h>
#include <mma.h>
#include <cstdint>
#include <math.h>

using namespace nvcuda;

// Problem: x[B=2,R=16,C=512,E=1024], H=16, D=64.  M = B*R*C = 16384.
#define MTOT 16384
#define EDIM 1024
#define CDIM 512
#define HNUM 16
#define DDIM 64
#define NBH  512

// Scratch (device globals: allocation-guard safe)
__device__ float g_q[16777216];
__device__ float g_k[16777216];
__device__ float g_v[16777216];
__device__ float g_ctx[16777216];   // tf32-rounded by attn epilogue
__device__ float g_xc[16777216];    // tf32-rounded copy of x
__device__ float g_wt[4 * 1048576]; // transposed + tf32-rounded weights [which][n][k]

__device__ __forceinline__ uint32_t smem_u32(const void* p) {
    uint32_t a;
    asm("{ .reg .u64 t; cvta.to.shared.u64 t, %1; cvt.u32.u64 %0, t; }"
        : "=r"(a) : "l"(p));
    return a;
}
__device__ __forceinline__ float to_tf32(float x) {
    uint32_t u;
    asm("cvt.rna.tf32.f32 %0, %1;" : "=r"(u) : "f"(x));
    return __uint_as_float(u);
}

// ---------------------------------------------------------------------------
// x -> tf32-rounded copy (g_xc)
// ---------------------------------------------------------------------------
__global__ __launch_bounds__(256) void convert_x_kernel(const float* __restrict__ x)
{
    const int n4 = 16777216 / 4;
    for (int i = blockIdx.x * blockDim.x + threadIdx.x; i < n4;
         i += gridDim.x * blockDim.x) {
        float4 v = ((const float4*)x)[i];
        v.x = to_tf32(v.x); v.y = to_tf32(v.y);
        v.z = to_tf32(v.z); v.w = to_tf32(v.w);
        ((float4*)g_xc)[i] = v;
    }
}

// ---------------------------------------------------------------------------
// Weight transpose + tf32 round: g_wt[which][n][k] = tf32(W[k][n])
// ---------------------------------------------------------------------------
__global__ __launch_bounds__(256) void transpose_w_kernel(
    const float* __restrict__ src, int which)
{
    __shared__ float t[32][33];
    const int bx = blockIdx.x * 32, by = blockIdx.y * 32;
    const int x = threadIdx.x, y = threadIdx.y;   // block (32, 8)
#pragma unroll
    for (int i = 0; i < 32; i += 8)
        t[y + i][x] = src[(size_t)(by + y + i) * EDIM + bx + x];
    __syncthreads();
    float* dst = g_wt + (size_t)which * EDIM * EDIM;
#pragma unroll
    for (int i = 0; i < 32; i += 8)
        dst[(size_t)(bx + y + i) * EDIM + by + x] = to_tf32(t[x][y + i]);
}

// ---------------------------------------------------------------------------
// wmma tf32 GEMM: D[m][n] = sum_k A[m][k] * Wt[n][k]  (+bias, *scale)
// BM=128, BN=128, BK=32, 2-stage cp.async, 8 warps (4m x 2n), warp = 32x64.
// mode 0/1/2 -> q/k/v (scatter to [bh][c][d]); mode 3 -> out (row-major).
// ---------------------------------------------------------------------------
#define LDAB 36                      // padded K-stride (floats), %4==0
#define STAGE_BYTES 36864            // A (128*36*4=18432) + B (18432)
#define GEMM_SMEM   73728            // 2 stages; Cs (128*132*4=67584) reuses it
#define LDC 132

__global__ __launch_bounds__(256) void gemm_tf32_kernel(
    const float* __restrict__ bias, float* __restrict__ outp, int mode)
{
    extern __shared__ char sm[];
    __shared__ float bias_s[128];

    const int tid = threadIdx.x, wid = tid >> 5;
    const int warp_m = wid >> 1, warp_n = wid & 1;
    const int m0 = blockIdx.y * 128, n0 = blockIdx.x * 128;

    const float* Ap = (mode == 3) ? g_ctx : g_xc;
    const float* Bp = g_wt + (size_t)mode * (EDIM * EDIM);
    float* dstp = (mode == 0) ? g_q : (mode == 1) ? g_k : (mode == 2) ? g_v : outp;

    if (tid < 32)
        *(float4*)(bias_s + tid * 4) = *(const float4*)(bias + n0 + tid * 4);

    const uint32_t smb = smem_u32(sm);
    const int c_row = tid >> 3, c_kq = tid & 7;   // 128 rows x 8 quads per 256-thread pass? no:
    // chunk c in [0,1024): row=c>>3, kq=c&7; thread does c = tid + i*256, i<4

    auto load_tile = [&](int t, int s) {
        const int k0 = t * 32;
        const uint32_t Ad = smb + s * STAGE_BYTES;
        const uint32_t Bd = Ad + 18432;
#pragma unroll
        for (int i = 0; i < 4; i++) {
            const int c = tid + i * 256;
            const int row = c >> 3, kq = c & 7;
            const float* ga = Ap + (size_t)(m0 + row) * EDIM + k0 + kq * 4;
            const float* gb = Bp + (size_t)(n0 + row) * EDIM + k0 + kq * 4;
            const uint32_t da = Ad + row * (LDAB * 4) + kq * 16;
            const uint32_t db = Bd + row * (LDAB * 4) + kq * 16;
            asm volatile("cp.async.cg.shared.global [%0], [%1], 16;"
                         :: "r"(da), "l"(ga) : "memory");
            asm volatile("cp.async.cg.shared.global [%0], [%1], 16;"
                         :: "r"(db), "l"(gb) : "memory");
        }
        asm volatile("cp.async.commit_group;" ::: "memory");
    };

    wmma::fragment<wmma::accumulator, 16, 16, 8, float> cf[2][4];
#pragma unroll
    for (int i = 0; i < 2; i++)
#pragma unroll
        for (int j = 0; j < 4; j++)
            wmma::fill_fragment(cf[i][j], 0.0f);

    load_tile(0, 0);

    for (int t = 0; t < 32; t++) {
        if (t + 1 < 32) {
            load_tile(t + 1, (t + 1) & 1);
            asm volatile("cp.async.wait_group 1;" ::: "memory");
        } else {
            asm volatile("cp.async.wait_group 0;" ::: "memory");
        }
        __syncthreads();

        const float* As = (const float*)(sm + (t & 1) * STAGE_BYTES);
        const float* Bs = As + 18432 / 4;

#pragma unroll
        for (int ks = 0; ks < 4; ks++) {
            const int k8 = ks * 8;
            wmma::fragment<wmma::matrix_a, 16, 16, 8, wmma::precision::tf32,
                           wmma::row_major> af[2];
            wmma::fragment<wmma::matrix_b, 16, 16, 8, wmma::precision::tf32,
                           wmma::col_major> bf[4];
#pragma unroll
            for (int i = 0; i < 2; i++)
                wmma::load_matrix_sync(af[i],
                    As + (warp_m * 32 + i * 16) * LDAB + k8, LDAB);
#pragma unroll
            for (int j = 0; j < 4; j++)
                wmma::load_matrix_sync(bf[j],
                    Bs + (warp_n * 64 + j * 16) * LDAB + k8, LDAB);
#pragma unroll
            for (int i = 0; i < 2; i++)
#pragma unroll
                for (int j = 0; j < 4; j++)
                    wmma::mma_sync(cf[i][j], af[i], bf[j], cf[i][j]);
        }
        __syncthreads();   // stage will be overwritten by load issued next iter
    }

    // Epilogue: dump accumulators to smem tile, then bias/scale/scatter
    float* Cs = (float*)sm;
#pragma unroll
    for (int i = 0; i < 2; i++)
#pragma unroll
        for (int j = 0; j < 4; j++)
            wmma::store_matrix_sync(
                Cs + (warp_m * 32 + i * 16) * LDC + warp_n * 64 + j * 16,
                cf[i][j], LDC, wmma::mem_row_major);
    __syncthreads();

    const float scale = (mode == 0) ? 0.125f : 1.0f;
#pragma unroll
    for (int i = 0; i < 16; i++) {
        const int e = (tid + i * 256) * 4;
        const int row = e >> 7, col = e & 127;
        const float* c = Cs + row * LDC + col;
        const float* b = bias_s + col;
        float4 v;
        v.x = (c[0] + b[0]) * scale;
        v.y = (c[1] + b[1]) * scale;
        v.z = (c[2] + b[2]) * scale;
        v.w = (c[3] + b[3]) * scale;
        const int m = m0 + row, n = n0 + col;
        if (mode < 3) {
            const int br = m >> 9, cp = m & 511;
            *(float4*)(dstp +
                ((size_t)(br * HNUM + (n >> 6)) * CDIM + cp) * DDIM + (n & 63)) = v;
        } else {
            *(float4*)(dstp + (size_t)m * EDIM + n) = v;
        }
    }
}

// ---------------------------------------------------------------------------
// Flash attention (fp32 SIMT, roofline-bound). ctx written ROW-MAJOR [m][e],
// tf32-rounded so the out-proj GEMM operand is RNA-rounded.
// ---------------------------------------------------------------------------
#define ATT_STRIDE 68
#define ATT_SMEM_FLOATS (4 * 64 * ATT_STRIDE)

__global__ __launch_bounds__(256) void attn_kernel()
{
    extern __shared__ float smf[];
    float* Qs = smf;
    float* Ks = Qs + 64 * ATT_STRIDE;
    float* Vs = Ks + 64 * ATT_STRIDE;
    float* Ps = Vs + 64 * ATT_STRIDE;

    const int blk = blockIdx.x;
    const int bh = blk >> 3, qb = blk & 7;
    const int t = threadIdx.x, tx = t & 15, ty = t >> 4;

    const float* qbase = g_q + (size_t)bh * (CDIM * DDIM) + qb * 64 * DDIM;
    const float* kbase = g_k + (size_t)bh * (CDIM * DDIM);
    const float* vbase = g_v + (size_t)bh * (CDIM * DDIM);

    for (int idx = t; idx < 4096; idx += 256) {
        int qr = idx >> 6, d = idx & 63;
        Qs[d * ATT_STRIDE + qr] = qbase[idx];
    }

    float m_i[4], l_i[4], o[4][4];
#pragma unroll
    for (int i = 0; i < 4; i++) {
        m_i[i] = -1e30f; l_i[i] = 0.f;
#pragma unroll
        for (int j = 0; j < 4; j++) o[i][j] = 0.f;
    }

    for (int kb = 0; kb < 8; kb++) {
        __syncthreads();
        for (int idx = t; idx < 4096; idx += 256) {
            int kr = idx >> 6, d = idx & 63;
            Ks[d * ATT_STRIDE + kr] = kbase[kb * 4096 + idx];
            Vs[kr * ATT_STRIDE + d] = vbase[kb * 4096 + idx];
        }
        __syncthreads();

        float s[4][4];
#pragma unroll
        for (int i = 0; i < 4; i++)
#pragma unroll
            for (int j = 0; j < 4; j++) s[i][j] = 0.f;

#pragma unroll 4
        for (int d = 0; d < 64; d++) {
            float4 aq = *(const float4*)&Qs[d * ATT_STRIDE + ty * 4];
            float4 bk = *(const float4*)&Ks[d * ATT_STRIDE + tx * 4];
            float a[4] = {aq.x, aq.y, aq.z, aq.w};
            float b[4] = {bk.x, bk.y, bk.z, bk.w};
#pragma unroll
            for (int i = 0; i < 4; i++)
#pragma unroll
                for (int j = 0; j < 4; j++)
                    s[i][j] += a[i] * b[j];
        }

#pragma unroll
        for (int i = 0; i < 4; i++) {
            float rm = fmaxf(fmaxf(s[i][0], s[i][1]), fmaxf(s[i][2], s[i][3]));
#pragma unroll
            for (int off = 8; off > 0; off >>= 1)
                rm = fmaxf(rm, __shfl_xor_sync(0xffffffffu, rm, off));
            float mn = fmaxf(m_i[i], rm);
            float corr = __expf(m_i[i] - mn);
            m_i[i] = mn;
            float ps = 0.f;
#pragma unroll
            for (int j = 0; j < 4; j++) {
                s[i][j] = __expf(s[i][j] - mn);
                ps += s[i][j];
            }
#pragma unroll
            for (int off = 8; off > 0; off >>= 1)
                ps += __shfl_xor_sync(0xffffffffu, ps, off);
            l_i[i] = l_i[i] * corr + ps;
#pragma unroll
            for (int j = 0; j < 4; j++) o[i][j] *= corr;
        }

#pragma unroll
        for (int i = 0; i < 4; i++)
#pragma unroll
            for (int j = 0; j < 4; j++)
                Ps[(tx * 4 + j) * ATT_STRIDE + ty * 4 + i] = s[i][j];
        __syncthreads();

#pragma unroll 4
        for (int kr = 0; kr < 64; kr++) {
            float4 ap = *(const float4*)&Ps[kr * ATT_STRIDE + ty * 4];
            float4 bv = *(const float4*)&Vs[kr * ATT_STRIDE + tx * 4];
            float a[4] = {ap.x, ap.y, ap.z, ap.w};
            float b[4] = {bv.x, bv.y, bv.z, bv.w};
#pragma unroll
            for (int i = 0; i < 4; i++)
#pragma unroll
                for (int j = 0; j < 4; j++)
                    o[i][j] += a[i] * b[j];
        }
    }

    // ctx row-major: row = (bh>>4)*512 + qb*64 + qr, col = (bh&15)*64 + d
    float* obase = g_ctx + ((size_t)(bh >> 4) * CDIM + qb * 64) * EDIM + (bh & 15) * DDIM;
#pragma unroll
    for (int i = 0; i < 4; i++) {
        float inv = 1.f / l_i[i];
        float4 v;
        v.x = to_tf32(o[i][0] * inv); v.y = to_tf32(o[i][1] * inv);
        v.z = to_tf32(o[i][2] * inv); v.w = to_tf32(o[i][3] * inv);
        *(float4*)(obase + (size_t)(ty * 4 + i) * EDIM + tx * 4) = v;
    }
}

// ---------------------------------------------------------------------------
extern "C" void kernel_launch(void* const* d_in, const int* in_sizes, int n_in,
                              void* d_out, int out_size)
{
    const float* x  = (const float*)d_in[0];
    const float* wq = (const float*)d_in[1];
    const float* bq = (const float*)d_in[2];
    const float* wk = (const float*)d_in[3];
    const float* bk = (const float*)d_in[4];
    const float* wv = (const float*)d_in[5];
    const float* bv = (const float*)d_in[6];
    const float* wo = (const float*)d_in[7];
    const float* bo = (const float*)d_in[8];
    float* out = (float*)d_out;

    convert_x_kernel<<<2048, 256>>>(x);

    dim3 tg(32, 32), tb(32, 8);
    transpose_w_kernel<<<tg, tb>>>(wq, 0);
    transpose_w_kernel<<<tg, tb>>>(wk, 1);
    transpose_w_kernel<<<tg, tb>>>(wv, 2);
    transpose_w_kernel<<<tg, tb>>>(wo, 3);

    cudaFuncSetAttribute(gemm_tf32_kernel,
                         cudaFuncAttributeMaxDynamicSharedMemorySize, GEMM_SMEM);
    dim3 gg(EDIM / 128, MTOT / 128);   // (8, 128)
    gemm_tf32_kernel<<<gg, 256, GEMM_SMEM>>>(bq, nullptr, 0);
    gemm_tf32_kernel<<<gg, 256, GEMM_SMEM>>>(bk, nullptr, 1);
    gemm_tf32_kernel<<<gg, 256, GEMM_SMEM>>>(bv, nullptr, 2);

    const int att_smem = ATT_SMEM_FLOATS * (int)sizeof(float);
    cudaFuncSetAttribute(attn_kernel,
                         cudaFuncAttributeMaxDynamicSharedMemorySize, att_smem);
    attn_kernel<<<NBH * 8, 256, att_smem>>>();

    gemm_tf32_kernel<<<gg, 256, GEMM_SMEM>>>(bo, out, 3);
}

// round 7
// speedup vs baseline: 1.2936x; 1.0401x over previous
#include <cuda_runtime.h>
#include <mma.h>
#include <cstdint>
#include <math.h>

using namespace nvcuda;

// Problem: x[B=2,R=16,C=512,E=1024], H=16, D=64.  M = B*R*C = 16384.
#define MTOT 16384
#define EDIM 1024
#define CDIM 512
#define HNUM 16
#define DDIM 64
#define NBH  512

// Scratch (device globals: allocation-guard safe)
__device__ float g_q[16777216];
__device__ float g_k[16777216];
__device__ float g_v[16777216];
__device__ float g_ctx[16777216];   // tf32-rounded by attn epilogue
__device__ float g_xc[16777216];    // tf32-rounded copy of x
__device__ float g_wt[4 * 1048576]; // transposed + tf32-rounded weights [which][n][k]

__device__ __forceinline__ uint32_t smem_u32(const void* p) {
    uint32_t a;
    asm("{ .reg .u64 t; cvta.to.shared.u64 t, %1; cvt.u32.u64 %0, t; }"
        : "=r"(a) : "l"(p));
    return a;
}
__device__ __forceinline__ float to_tf32(float x) {
    uint32_t u;
    asm("cvt.rna.tf32.f32 %0, %1;" : "=r"(u) : "f"(x));
    return __uint_as_float(u);
}

// ---------------------------------------------------------------------------
// x -> tf32-rounded copy (g_xc)
// ---------------------------------------------------------------------------
__global__ __launch_bounds__(256) void convert_x_kernel(const float* __restrict__ x)
{
    const int n4 = 16777216 / 4;
    for (int i = blockIdx.x * blockDim.x + threadIdx.x; i < n4;
         i += gridDim.x * blockDim.x) {
        float4 v = ((const float4*)x)[i];
        v.x = to_tf32(v.x); v.y = to_tf32(v.y);
        v.z = to_tf32(v.z); v.w = to_tf32(v.w);
        ((float4*)g_xc)[i] = v;
    }
}

// ---------------------------------------------------------------------------
// Weight transpose + tf32 round: g_wt[which][n][k] = tf32(W[k][n])
// ---------------------------------------------------------------------------
__global__ __launch_bounds__(256) void transpose_w_kernel(
    const float* __restrict__ src, int which)
{
    __shared__ float t[32][33];
    const int bx = blockIdx.x * 32, by = blockIdx.y * 32;
    const int x = threadIdx.x, y = threadIdx.y;   // block (32, 8)
#pragma unroll
    for (int i = 0; i < 32; i += 8)
        t[y + i][x] = src[(size_t)(by + y + i) * EDIM + bx + x];
    __syncthreads();
    float* dst = g_wt + (size_t)which * EDIM * EDIM;
#pragma unroll
    for (int i = 0; i < 32; i += 8)
        dst[(size_t)(bx + y + i) * EDIM + by + x] = to_tf32(t[x][y + i]);
}

// ---------------------------------------------------------------------------
// wmma tf32 GEMM: D[m][n] = sum_k A[m][k] * Wt[n][k]  (+bias, *scale)
// BM=128, BN=128, BK=32, 2-stage cp.async, 8 warps (4m x 2n).
// mode 0/1/2 -> q/k/v (scatter to [bh][c][d], tf32-rounded for the attention
// mma); mode 3 -> final out (row-major, full fp32).
// ---------------------------------------------------------------------------
#define LDAB 36
#define STAGE_BYTES 36864
#define GEMM_SMEM   73728
#define LDC 132

__global__ __launch_bounds__(256) void gemm_tf32_kernel(
    const float* __restrict__ bias, float* __restrict__ outp, int mode)
{
    extern __shared__ char sm[];
    __shared__ float bias_s[128];

    const int tid = threadIdx.x, wid = tid >> 5;
    const int warp_m = wid >> 1, warp_n = wid & 1;
    const int m0 = blockIdx.y * 128, n0 = blockIdx.x * 128;

    const float* Ap = (mode == 3) ? g_ctx : g_xc;
    const float* Bp = g_wt + (size_t)mode * (EDIM * EDIM);
    float* dstp = (mode == 0) ? g_q : (mode == 1) ? g_k : (mode == 2) ? g_v : outp;

    if (tid < 32)
        *(float4*)(bias_s + tid * 4) = *(const float4*)(bias + n0 + tid * 4);

    const uint32_t smb = smem_u32(sm);

    auto load_tile = [&](int t, int s) {
        const int k0 = t * 32;
        const uint32_t Ad = smb + s * STAGE_BYTES;
        const uint32_t Bd = Ad + 18432;
#pragma unroll
        for (int i = 0; i < 4; i++) {
            const int c = tid + i * 256;
            const int row = c >> 3, kq = c & 7;
            const float* ga = Ap + (size_t)(m0 + row) * EDIM + k0 + kq * 4;
            const float* gb = Bp + (size_t)(n0 + row) * EDIM + k0 + kq * 4;
            const uint32_t da = Ad + row * (LDAB * 4) + kq * 16;
            const uint32_t db = Bd + row * (LDAB * 4) + kq * 16;
            asm volatile("cp.async.cg.shared.global [%0], [%1], 16;"
                         :: "r"(da), "l"(ga) : "memory");
            asm volatile("cp.async.cg.shared.global [%0], [%1], 16;"
                         :: "r"(db), "l"(gb) : "memory");
        }
        asm volatile("cp.async.commit_group;" ::: "memory");
    };

    wmma::fragment<wmma::accumulator, 16, 16, 8, float> cf[2][4];
#pragma unroll
    for (int i = 0; i < 2; i++)
#pragma unroll
        for (int j = 0; j < 4; j++)
            wmma::fill_fragment(cf[i][j], 0.0f);

    load_tile(0, 0);

    for (int t = 0; t < 32; t++) {
        if (t + 1 < 32) {
            load_tile(t + 1, (t + 1) & 1);
            asm volatile("cp.async.wait_group 1;" ::: "memory");
        } else {
            asm volatile("cp.async.wait_group 0;" ::: "memory");
        }
        __syncthreads();

        const float* As = (const float*)(sm + (t & 1) * STAGE_BYTES);
        const float* Bs = As + 18432 / 4;

#pragma unroll
        for (int ks = 0; ks < 4; ks++) {
            const int k8 = ks * 8;
            wmma::fragment<wmma::matrix_a, 16, 16, 8, wmma::precision::tf32,
                           wmma::row_major> af[2];
            wmma::fragment<wmma::matrix_b, 16, 16, 8, wmma::precision::tf32,
                           wmma::col_major> bf[4];
#pragma unroll
            for (int i = 0; i < 2; i++)
                wmma::load_matrix_sync(af[i],
                    As + (warp_m * 32 + i * 16) * LDAB + k8, LDAB);
#pragma unroll
            for (int j = 0; j < 4; j++)
                wmma::load_matrix_sync(bf[j],
                    Bs + (warp_n * 64 + j * 16) * LDAB + k8, LDAB);
#pragma unroll
            for (int i = 0; i < 2; i++)
#pragma unroll
                for (int j = 0; j < 4; j++)
                    wmma::mma_sync(cf[i][j], af[i], bf[j], cf[i][j]);
        }
        __syncthreads();
    }

    float* Cs = (float*)sm;
#pragma unroll
    for (int i = 0; i < 2; i++)
#pragma unroll
        for (int j = 0; j < 4; j++)
            wmma::store_matrix_sync(
                Cs + (warp_m * 32 + i * 16) * LDC + warp_n * 64 + j * 16,
                cf[i][j], LDC, wmma::mem_row_major);
    __syncthreads();

    const float scale = (mode == 0) ? 0.125f : 1.0f;
#pragma unroll
    for (int i = 0; i < 16; i++) {
        const int e = (tid + i * 256) * 4;
        const int row = e >> 7, col = e & 127;
        const float* c = Cs + row * LDC + col;
        const float* b = bias_s + col;
        float4 v;
        v.x = (c[0] + b[0]) * scale;
        v.y = (c[1] + b[1]) * scale;
        v.z = (c[2] + b[2]) * scale;
        v.w = (c[3] + b[3]) * scale;
        const int m = m0 + row, n = n0 + col;
        if (mode < 3) {
            // round q/k/v to tf32 so the attention mma sees exact operands
            v.x = to_tf32(v.x); v.y = to_tf32(v.y);
            v.z = to_tf32(v.z); v.w = to_tf32(v.w);
            const int br = m >> 9, cp = m & 511;
            *(float4*)(dstp +
                ((size_t)(br * HNUM + (n >> 6)) * CDIM + cp) * DDIM + (n & 63)) = v;
        } else {
            *(float4*)(dstp + (size_t)m * EDIM + n) = v;
        }
    }
}

// ---------------------------------------------------------------------------
// Flash attention, wmma tf32 tensorized.
// CTA = (bh, 64-row q-block), 256 threads (8 warps).
//   S = Q K^T   : 16 wmma m16n16k8 tiles (warp w -> ti=w>>1, tj=(w&1)*2+{0,1})
//   softmax     : 4 threads per row (thread t -> row t>>2, cols (t&3)*16..+16),
//                 m/l/corr thread-local, shfl over the 4-lane group
//   O += P V    : same wmma tiling -> Ts, then per-thread register O update
// Smem: Qs,Ks,Vs,Ss,Ts @ 64x68 = 87 KB -> 2 CTAs/SM.
// ---------------------------------------------------------------------------
#define ASTR 68
#define ATT_SMEM (5 * 64 * ASTR * 4)

__global__ __launch_bounds__(256) void attn_kernel()
{
    extern __shared__ float smf[];
    float* Qs = smf;
    float* Ks = Qs + 64 * ASTR;
    float* Vs = Ks + 64 * ASTR;
    float* Ss = Vs + 64 * ASTR;
    float* Ts = Ss + 64 * ASTR;

    const int blk = blockIdx.x;
    const int bh = blk >> 3, qb = blk & 7;
    const int t = threadIdx.x;
    const int w = t >> 5;
    const int ti = w >> 1;            // S/PV row-tile (0..3)
    const int tj0 = (w & 1) * 2;      // S/PV col-tiles {tj0, tj0+1}
    const int srow = t >> 2;          // softmax row (0..63)
    const int scol = (t & 3) * 16;    // softmax col base

    const float* qbase = g_q + (size_t)bh * (CDIM * DDIM) + qb * 64 * DDIM;
    const float* kbase = g_k + (size_t)bh * (CDIM * DDIM);
    const float* vbase = g_v + (size_t)bh * (CDIM * DDIM);

    // Load Q (natural [qr][d] row-major)
    for (int idx = t; idx < 4096; idx += 256) {
        int qr = idx >> 6, d = idx & 63;
        Qs[qr * ASTR + d] = qbase[idx];
    }

    float m_i = -1e30f, l_i = 0.f;
    float o[16];
#pragma unroll
    for (int j = 0; j < 16; j++) o[j] = 0.f;

    for (int kb = 0; kb < 8; kb++) {
        __syncthreads();   // prev iter consumers of Ks/Vs/Ss/Ts done
        for (int idx = t; idx < 4096; idx += 256) {
            int kr = idx >> 6, d = idx & 63;
            Ks[kr * ASTR + d] = kbase[kb * 4096 + idx];
            Vs[kr * ASTR + d] = vbase[kb * 4096 + idx];
        }
        __syncthreads();

        // ---- S = Q K^T (wmma) ----
        {
            wmma::fragment<wmma::accumulator, 16, 16, 8, float> c0, c1;
            wmma::fill_fragment(c0, 0.0f);
            wmma::fill_fragment(c1, 0.0f);
#pragma unroll
            for (int ks = 0; ks < 8; ks++) {
                const int k8 = ks * 8;
                wmma::fragment<wmma::matrix_a, 16, 16, 8, wmma::precision::tf32,
                               wmma::row_major> af;
                wmma::fragment<wmma::matrix_b, 16, 16, 8, wmma::precision::tf32,
                               wmma::col_major> bf0, bf1;
                wmma::load_matrix_sync(af, Qs + ti * 16 * ASTR + k8, ASTR);
                wmma::load_matrix_sync(bf0, Ks + tj0 * 16 * ASTR + k8, ASTR);
                wmma::load_matrix_sync(bf1, Ks + (tj0 + 1) * 16 * ASTR + k8, ASTR);
                wmma::mma_sync(c0, af, bf0, c0);
                wmma::mma_sync(c1, af, bf1, c1);
            }
            wmma::store_matrix_sync(Ss + ti * 16 * ASTR + tj0 * 16, c0, ASTR,
                                    wmma::mem_row_major);
            wmma::store_matrix_sync(Ss + ti * 16 * ASTR + (tj0 + 1) * 16, c1, ASTR,
                                    wmma::mem_row_major);
        }
        __syncthreads();

        // ---- online softmax (4 threads per row) ----
        float corr;
        {
            float* srw = Ss + srow * ASTR + scol;
            float s[16];
#pragma unroll
            for (int j = 0; j < 16; j++) s[j] = srw[j];
            float rm = s[0];
#pragma unroll
            for (int j = 1; j < 16; j++) rm = fmaxf(rm, s[j]);
            rm = fmaxf(rm, __shfl_xor_sync(0xffffffffu, rm, 1));
            rm = fmaxf(rm, __shfl_xor_sync(0xffffffffu, rm, 2));
            const float mn = fmaxf(m_i, rm);
            corr = __expf(m_i - mn);
            m_i = mn;
            float ps = 0.f;
#pragma unroll
            for (int j = 0; j < 16; j++) {
                s[j] = __expf(s[j] - mn);
                ps += s[j];
            }
            ps += __shfl_xor_sync(0xffffffffu, ps, 1);
            ps += __shfl_xor_sync(0xffffffffu, ps, 2);
            l_i = l_i * corr + ps;
#pragma unroll
            for (int j = 0; j < 16; j++) srw[j] = to_tf32(s[j]);
        }
        __syncthreads();

        // ---- T = P V (wmma) ----
        {
            wmma::fragment<wmma::accumulator, 16, 16, 8, float> c0, c1;
            wmma::fill_fragment(c0, 0.0f);
            wmma::fill_fragment(c1, 0.0f);
#pragma unroll
            for (int ks = 0; ks < 8; ks++) {
                const int k8 = ks * 8;
                wmma::fragment<wmma::matrix_a, 16, 16, 8, wmma::precision::tf32,
                               wmma::row_major> af;
                wmma::fragment<wmma::matrix_b, 16, 16, 8, wmma::precision::tf32,
                               wmma::row_major> bf0, bf1;
                wmma::load_matrix_sync(af, Ss + ti * 16 * ASTR + k8, ASTR);
                wmma::load_matrix_sync(bf0, Vs + k8 * ASTR + tj0 * 16, ASTR);
                wmma::load_matrix_sync(bf1, Vs + k8 * ASTR + (tj0 + 1) * 16, ASTR);
                wmma::mma_sync(c0, af, bf0, c0);
                wmma::mma_sync(c1, af, bf1, c1);
            }
            wmma::store_matrix_sync(Ts + ti * 16 * ASTR + tj0 * 16, c0, ASTR,
                                    wmma::mem_row_major);
            wmma::store_matrix_sync(Ts + ti * 16 * ASTR + (tj0 + 1) * 16, c1, ASTR,
                                    wmma::mem_row_major);
        }
        __syncthreads();

        // ---- O update (register-resident, thread owns row srow cols scol..+16)
        {
            const float* trw = Ts + srow * ASTR + scol;
#pragma unroll
            for (int j = 0; j < 16; j++)
                o[j] = o[j] * corr + trw[j];
        }
    }

    // ---- normalize + write ctx (row-major, tf32-rounded) ----
    const float inv = 1.f / l_i;
    float* obase = g_ctx + ((size_t)(bh >> 4) * CDIM + qb * 64) * EDIM + (bh & 15) * DDIM;
    float* orow = obase + (size_t)srow * EDIM + scol;
#pragma unroll
    for (int j4 = 0; j4 < 4; j4++) {
        float4 v;
        v.x = to_tf32(o[j4 * 4 + 0] * inv);
        v.y = to_tf32(o[j4 * 4 + 1] * inv);
        v.z = to_tf32(o[j4 * 4 + 2] * inv);
        v.w = to_tf32(o[j4 * 4 + 3] * inv);
        *(float4*)(orow + j4 * 4) = v;
    }
}

// ---------------------------------------------------------------------------
extern "C" void kernel_launch(void* const* d_in, const int* in_sizes, int n_in,
                              void* d_out, int out_size)
{
    const float* x  = (const float*)d_in[0];
    const float* wq = (const float*)d_in[1];
    const float* bq = (const float*)d_in[2];
    const float* wk = (const float*)d_in[3];
    const float* bk = (const float*)d_in[4];
    const float* wv = (const float*)d_in[5];
    const float* bv = (const float*)d_in[6];
    const float* wo = (const float*)d_in[7];
    const float* bo = (const float*)d_in[8];
    float* out = (float*)d_out;

    convert_x_kernel<<<2048, 256>>>(x);

    dim3 tg(32, 32), tb(32, 8);
    transpose_w_kernel<<<tg, tb>>>(wq, 0);
    transpose_w_kernel<<<tg, tb>>>(wk, 1);
    transpose_w_kernel<<<tg, tb>>>(wv, 2);
    transpose_w_kernel<<<tg, tb>>>(wo, 3);

    cudaFuncSetAttribute(gemm_tf32_kernel,
                         cudaFuncAttributeMaxDynamicSharedMemorySize, GEMM_SMEM);
    dim3 gg(EDIM / 128, MTOT / 128);   // (8, 128)
    gemm_tf32_kernel<<<gg, 256, GEMM_SMEM>>>(bq, nullptr, 0);
    gemm_tf32_kernel<<<gg, 256, GEMM_SMEM>>>(bk, nullptr, 1);
    gemm_tf32_kernel<<<gg, 256, GEMM_SMEM>>>(bv, nullptr, 2);

    cudaFuncSetAttribute(attn_kernel,
                         cudaFuncAttributeMaxDynamicSharedMemorySize, ATT_SMEM);
    attn_kernel<<<NBH * 8, 256, ATT_SMEM>>>();

    gemm_tf32_kernel<<<gg, 256, GEMM_SMEM>>>(bo, out, 3);
}

// round 8
// speedup vs baseline: 4.4576x; 3.4459x over previous
#include <cuda_runtime.h>
#include <mma.h>
#include <cuda_fp16.h>
#include <cstdint>
#include <math.h>

using namespace nvcuda;

// Problem: x[B=2,R=16,C=512,E=1024], H=16, D=64.  M = B*R*C = 16384.
#define MTOT 16384
#define EDIM 1024
#define CDIM 512
#define HNUM 16
#define DDIM 64
#define NBH  512

// Scratch (device globals: allocation-guard safe). All MMA operands fp16.
__device__ __half g_qh[16777216];
__device__ __half g_kh[16777216];
__device__ __half g_vh[16777216];
__device__ __half g_ctxh[16777216];
__device__ __half g_xh[16777216];
__device__ __half g_wth[4 * 1048576];   // transposed weights [which][n][k]

__device__ __forceinline__ uint32_t smem_u32(const void* p) {
    uint32_t a;
    asm("{ .reg .u64 t; cvta.to.shared.u64 t, %1; cvt.u32.u64 %0, t; }"
        : "=r"(a) : "l"(p));
    return a;
}

// ---------------------------------------------------------------------------
// x -> fp16 copy
// ---------------------------------------------------------------------------
__global__ __launch_bounds__(256) void convert_x_kernel(const float* __restrict__ x)
{
    const int n4 = 16777216 / 4;
    for (int i = blockIdx.x * blockDim.x + threadIdx.x; i < n4;
         i += gridDim.x * blockDim.x) {
        float4 v = ((const float4*)x)[i];
        __half2 h0 = __floats2half2_rn(v.x, v.y);
        __half2 h1 = __floats2half2_rn(v.z, v.w);
        ((__half2*)g_xh)[i * 2 + 0] = h0;
        ((__half2*)g_xh)[i * 2 + 1] = h1;
    }
}

// ---------------------------------------------------------------------------
// Weight transpose + fp16: g_wth[which][n][k] = h(W[k][n])
// ---------------------------------------------------------------------------
__global__ __launch_bounds__(256) void transpose_w_kernel(
    const float* __restrict__ src, int which)
{
    __shared__ float t[32][33];
    const int bx = blockIdx.x * 32, by = blockIdx.y * 32;
    const int x = threadIdx.x, y = threadIdx.y;   // block (32, 8)
#pragma unroll
    for (int i = 0; i < 32; i += 8)
        t[y + i][x] = src[(size_t)(by + y + i) * EDIM + bx + x];
    __syncthreads();
    __half* dst = g_wth + (size_t)which * EDIM * EDIM;
#pragma unroll
    for (int i = 0; i < 32; i += 8)
        dst[(size_t)(bx + y + i) * EDIM + by + x] = __float2half_rn(t[x][y + i]);
}

// ---------------------------------------------------------------------------
// fp16 wmma GEMM: D[m][n] = sum_k A[m][k] * Wt[n][k]  (+bias, *scale)
// BM=128, BN=128, BK=32 (2 k-steps of 16), 2-stage cp.async, 8 warps (4m x 2n).
// mode 0/1/2 -> q/k/v (fp16, scatter to [bh][c][d]); mode 3 -> out (fp32).
// ---------------------------------------------------------------------------
#define LDH 40                      // padded K-stride in halves (80B)
#define STAGE_BYTES 20480           // A (128*40*2=10240) + B (10240)
#define GEMM_SMEM   67584           // Cs float 128*132*4 dominates
#define LDC 132

__global__ __launch_bounds__(256) void gemm_h_kernel(
    const float* __restrict__ bias, float* __restrict__ outp, int mode)
{
    extern __shared__ char sm[];
    __shared__ float bias_s[128];

    const int tid = threadIdx.x, wid = tid >> 5;
    const int warp_m = wid >> 1, warp_n = wid & 1;
    const int m0 = blockIdx.y * 128, n0 = blockIdx.x * 128;

    const __half* Ap = (mode == 3) ? g_ctxh : g_xh;
    const __half* Bp = g_wth + (size_t)mode * (EDIM * EDIM);

    if (tid < 32)
        *(float4*)(bias_s + tid * 4) = *(const float4*)(bias + n0 + tid * 4);

    const uint32_t smb = smem_u32(sm);

    // Stage: A tile 128 rows x 32 halves (4 chunks of 8), B same.
    auto load_tile = [&](int t, int s) {
        const int k0 = t * 32;
        const uint32_t Ad = smb + s * STAGE_BYTES;
        const uint32_t Bd = Ad + 10240;
#pragma unroll
        for (int i = 0; i < 2; i++) {
            const int c = tid + i * 256;       // 0..511
            const int row = c >> 2, kq = c & 3;
            const __half* ga = Ap + (size_t)(m0 + row) * EDIM + k0 + kq * 8;
            const __half* gb = Bp + (size_t)(n0 + row) * EDIM + k0 + kq * 8;
            const uint32_t da = Ad + row * (LDH * 2) + kq * 16;
            const uint32_t db = Bd + row * (LDH * 2) + kq * 16;
            asm volatile("cp.async.cg.shared.global [%0], [%1], 16;"
                         :: "r"(da), "l"(ga) : "memory");
            asm volatile("cp.async.cg.shared.global [%0], [%1], 16;"
                         :: "r"(db), "l"(gb) : "memory");
        }
        asm volatile("cp.async.commit_group;" ::: "memory");
    };

    wmma::fragment<wmma::accumulator, 16, 16, 16, float> cf[2][4];
#pragma unroll
    for (int i = 0; i < 2; i++)
#pragma unroll
        for (int j = 0; j < 4; j++)
            wmma::fill_fragment(cf[i][j], 0.0f);

    load_tile(0, 0);

    for (int t = 0; t < 32; t++) {
        if (t + 1 < 32) {
            load_tile(t + 1, (t + 1) & 1);
            asm volatile("cp.async.wait_group 1;" ::: "memory");
        } else {
            asm volatile("cp.async.wait_group 0;" ::: "memory");
        }
        __syncthreads();

        const __half* As = (const __half*)(sm + (t & 1) * STAGE_BYTES);
        const __half* Bs = As + 10240 / 2;

#pragma unroll
        for (int ks = 0; ks < 2; ks++) {
            const int k16 = ks * 16;
            wmma::fragment<wmma::matrix_a, 16, 16, 16, __half, wmma::row_major> af[2];
            wmma::fragment<wmma::matrix_b, 16, 16, 16, __half, wmma::col_major> bf[4];
#pragma unroll
            for (int i = 0; i < 2; i++)
                wmma::load_matrix_sync(af[i],
                    As + (warp_m * 32 + i * 16) * LDH + k16, LDH);
#pragma unroll
            for (int j = 0; j < 4; j++)
                wmma::load_matrix_sync(bf[j],
                    Bs + (warp_n * 64 + j * 16) * LDH + k16, LDH);
#pragma unroll
            for (int i = 0; i < 2; i++)
#pragma unroll
                for (int j = 0; j < 4; j++)
                    wmma::mma_sync(cf[i][j], af[i], bf[j], cf[i][j]);
        }
        __syncthreads();
    }

    float* Cs = (float*)sm;
#pragma unroll
    for (int i = 0; i < 2; i++)
#pragma unroll
        for (int j = 0; j < 4; j++)
            wmma::store_matrix_sync(
                Cs + (warp_m * 32 + i * 16) * LDC + warp_n * 64 + j * 16,
                cf[i][j], LDC, wmma::mem_row_major);
    __syncthreads();

    const float scale = (mode == 0) ? 0.125f : 1.0f;
    __half* dsth = (mode == 0) ? g_qh : (mode == 1) ? g_kh : g_vh;
#pragma unroll
    for (int i = 0; i < 16; i++) {
        const int e = (tid + i * 256) * 4;
        const int row = e >> 7, col = e & 127;
        const float* c = Cs + row * LDC + col;
        const float* b = bias_s + col;
        float4 v;
        v.x = (c[0] + b[0]) * scale;
        v.y = (c[1] + b[1]) * scale;
        v.z = (c[2] + b[2]) * scale;
        v.w = (c[3] + b[3]) * scale;
        const int m = m0 + row, n = n0 + col;
        if (mode < 3) {
            const int br = m >> 9, cp = m & 511;
            __half2* d2 = (__half2*)(dsth +
                ((size_t)(br * HNUM + (n >> 6)) * CDIM + cp) * DDIM + (n & 63));
            d2[0] = __floats2half2_rn(v.x, v.y);
            d2[1] = __floats2half2_rn(v.z, v.w);
        } else {
            *(float4*)(outp + (size_t)m * EDIM + n) = v;
        }
    }
}

// ---------------------------------------------------------------------------
// Flash attention, fp16 wmma (m16n16k16).
// CTA = (bh, 64-row q-block), 256 threads (8 warps, 4m x 2n over 64x64).
// Smem: Ss,Ts float 64x68; Qs,Ks,Vs,Ps half 64x72.  Total 70 KB -> 3 CTAs/SM.
// ---------------------------------------------------------------------------
#define ASTR 68     // float tile stride
#define HSTR 72     // half tile stride
#define OFF_SS 0
#define OFF_TS (64 * ASTR * 4)
#define OFF_QS (2 * 64 * ASTR * 4)
#define OFF_KS (OFF_QS + 64 * HSTR * 2)
#define OFF_VS (OFF_KS + 64 * HSTR * 2)
#define OFF_PS (OFF_VS + 64 * HSTR * 2)
#define ATT_SMEM (OFF_PS + 64 * HSTR * 2)

__global__ __launch_bounds__(256) void attn_kernel()
{
    extern __shared__ char smc[];
    float* Ss = (float*)(smc + OFF_SS);
    float* Ts = (float*)(smc + OFF_TS);
    __half* Qs = (__half*)(smc + OFF_QS);
    __half* Ks = (__half*)(smc + OFF_KS);
    __half* Vs = (__half*)(smc + OFF_VS);
    __half* Ps = (__half*)(smc + OFF_PS);

    const int blk = blockIdx.x;
    const int bh = blk >> 3, qb = blk & 7;
    const int t = threadIdx.x;
    const int w = t >> 5;
    const int ti = w >> 1;            // row-tile (0..3)
    const int tj0 = (w & 1) * 2;      // col-tiles {tj0, tj0+1}
    const int srow = t >> 2;          // softmax row (0..63)
    const int scol = (t & 3) * 16;    // softmax col base

    const __half* qbase = g_qh + (size_t)bh * (CDIM * DDIM) + qb * 64 * DDIM;
    const __half* kbase = g_kh + (size_t)bh * (CDIM * DDIM);
    const __half* vbase = g_vh + (size_t)bh * (CDIM * DDIM);

    // Load Q tile ([qr][d] row-major, uint4 = 8 halves)
    for (int c = t; c < 512; c += 256) {
        const int qr = c >> 3, c8 = (c & 7) * 8;
        *(uint4*)&Qs[qr * HSTR + c8] = *(const uint4*)(qbase + qr * 64 + c8);
    }

    float m_i = -1e30f, l_i = 0.f;
    float o[16];
#pragma unroll
    for (int j = 0; j < 16; j++) o[j] = 0.f;

    for (int kb = 0; kb < 8; kb++) {
        __syncthreads();
        for (int c = t; c < 512; c += 256) {
            const int kr = c >> 3, c8 = (c & 7) * 8;
            *(uint4*)&Ks[kr * HSTR + c8] =
                *(const uint4*)(kbase + kb * 4096 + kr * 64 + c8);
            *(uint4*)&Vs[kr * HSTR + c8] =
                *(const uint4*)(vbase + kb * 4096 + kr * 64 + c8);
        }
        __syncthreads();

        // ---- S = Q K^T ----
        {
            wmma::fragment<wmma::accumulator, 16, 16, 16, float> c0, c1;
            wmma::fill_fragment(c0, 0.0f);
            wmma::fill_fragment(c1, 0.0f);
#pragma unroll
            for (int ks = 0; ks < 4; ks++) {
                const int k16 = ks * 16;
                wmma::fragment<wmma::matrix_a, 16, 16, 16, __half, wmma::row_major> af;
                wmma::fragment<wmma::matrix_b, 16, 16, 16, __half, wmma::col_major> bf0, bf1;
                wmma::load_matrix_sync(af, Qs + ti * 16 * HSTR + k16, HSTR);
                wmma::load_matrix_sync(bf0, Ks + tj0 * 16 * HSTR + k16, HSTR);
                wmma::load_matrix_sync(bf1, Ks + (tj0 + 1) * 16 * HSTR + k16, HSTR);
                wmma::mma_sync(c0, af, bf0, c0);
                wmma::mma_sync(c1, af, bf1, c1);
            }
            wmma::store_matrix_sync(Ss + ti * 16 * ASTR + tj0 * 16, c0, ASTR,
                                    wmma::mem_row_major);
            wmma::store_matrix_sync(Ss + ti * 16 * ASTR + (tj0 + 1) * 16, c1, ASTR,
                                    wmma::mem_row_major);
        }
        __syncthreads();

        // ---- online softmax (4 threads per row) ----
        float corr;
        {
            const float* srw = Ss + srow * ASTR + scol;
            float s[16];
#pragma unroll
            for (int j = 0; j < 16; j++) s[j] = srw[j];
            float rm = s[0];
#pragma unroll
            for (int j = 1; j < 16; j++) rm = fmaxf(rm, s[j]);
            rm = fmaxf(rm, __shfl_xor_sync(0xffffffffu, rm, 1));
            rm = fmaxf(rm, __shfl_xor_sync(0xffffffffu, rm, 2));
            const float mn = fmaxf(m_i, rm);
            corr = __expf(m_i - mn);
            m_i = mn;
            float ps = 0.f;
#pragma unroll
            for (int j = 0; j < 16; j++) {
                s[j] = __expf(s[j] - mn);
                ps += s[j];
            }
            ps += __shfl_xor_sync(0xffffffffu, ps, 1);
            ps += __shfl_xor_sync(0xffffffffu, ps, 2);
            l_i = l_i * corr + ps;
            __half2* prw = (__half2*)(Ps + srow * HSTR + scol);
#pragma unroll
            for (int j = 0; j < 8; j++)
                prw[j] = __floats2half2_rn(s[j * 2], s[j * 2 + 1]);
        }
        __syncthreads();

        // ---- T = P V ----
        {
            wmma::fragment<wmma::accumulator, 16, 16, 16, float> c0, c1;
            wmma::fill_fragment(c0, 0.0f);
            wmma::fill_fragment(c1, 0.0f);
#pragma unroll
            for (int ks = 0; ks < 4; ks++) {
                const int k16 = ks * 16;
                wmma::fragment<wmma::matrix_a, 16, 16, 16, __half, wmma::row_major> af;
                wmma::fragment<wmma::matrix_b, 16, 16, 16, __half, wmma::row_major> bf0, bf1;
                wmma::load_matrix_sync(af, Ps + ti * 16 * HSTR + k16, HSTR);
                wmma::load_matrix_sync(bf0, Vs + k16 * HSTR + tj0 * 16, HSTR);
                wmma::load_matrix_sync(bf1, Vs + k16 * HSTR + (tj0 + 1) * 16, HSTR);
                wmma::mma_sync(c0, af, bf0, c0);
                wmma::mma_sync(c1, af, bf1, c1);
            }
            wmma::store_matrix_sync(Ts + ti * 16 * ASTR + tj0 * 16, c0, ASTR,
                                    wmma::mem_row_major);
            wmma::store_matrix_sync(Ts + ti * 16 * ASTR + (tj0 + 1) * 16, c1, ASTR,
                                    wmma::mem_row_major);
        }
        __syncthreads();

        // ---- O update (registers; thread owns row srow, cols scol..scol+15) ----
        {
            const float* trw = Ts + srow * ASTR + scol;
#pragma unroll
            for (int j = 0; j < 16; j++)
                o[j] = o[j] * corr + trw[j];
        }
    }

    // ---- normalize + write ctx (fp16, row-major) ----
    const float inv = 1.f / l_i;
    __half* obase = g_ctxh + ((size_t)(bh >> 4) * CDIM + qb * 64) * EDIM + (bh & 15) * DDIM;
    __half2* orow = (__half2*)(obase + (size_t)srow * EDIM + scol);
#pragma unroll
    for (int j = 0; j < 8; j++)
        orow[j] = __floats2half2_rn(o[j * 2] * inv, o[j * 2 + 1] * inv);
}

// ---------------------------------------------------------------------------
extern "C" void kernel_launch(void* const* d_in, const int* in_sizes, int n_in,
                              void* d_out, int out_size)
{
    const float* x  = (const float*)d_in[0];
    const float* wq = (const float*)d_in[1];
    const float* bq = (const float*)d_in[2];
    const float* wk = (const float*)d_in[3];
    const float* bk = (const float*)d_in[4];
    const float* wv = (const float*)d_in[5];
    const float* bv = (const float*)d_in[6];
    const float* wo = (const float*)d_in[7];
    const float* bo = (const float*)d_in[8];
    float* out = (float*)d_out;

    convert_x_kernel<<<2048, 256>>>(x);

    dim3 tg(32, 32), tb(32, 8);
    transpose_w_kernel<<<tg, tb>>>(wq, 0);
    transpose_w_kernel<<<tg, tb>>>(wk, 1);
    transpose_w_kernel<<<tg, tb>>>(wv, 2);
    transpose_w_kernel<<<tg, tb>>>(wo, 3);

    cudaFuncSetAttribute(gemm_h_kernel,
                         cudaFuncAttributeMaxDynamicSharedMemorySize, GEMM_SMEM);
    dim3 gg(EDIM / 128, MTOT / 128);   // (8, 128)
    gemm_h_kernel<<<gg, 256, GEMM_SMEM>>>(bq, nullptr, 0);
    gemm_h_kernel<<<gg, 256, GEMM_SMEM>>>(bk, nullptr, 1);
    gemm_h_kernel<<<gg, 256, GEMM_SMEM>>>(bv, nullptr, 2);

    cudaFuncSetAttribute(attn_kernel,
                         cudaFuncAttributeMaxDynamicSharedMemorySize, ATT_SMEM);
    attn_kernel<<<NBH * 8, 256, ATT_SMEM>>>();

    gemm_h_kernel<<<gg, 256, GEMM_SMEM>>>(bo, out, 3);
}

// round 9
// speedup vs baseline: 5.2617x; 1.1804x over previous
#include <cuda_runtime.h>
#include <mma.h>
#include <cuda_fp16.h>
#include <cstdint>
#include <math.h>

using namespace nvcuda;

#define MTOT 16384
#define EDIM 1024
#define CDIM 512
#define HNUM 16
#define DDIM 64
#define NBH  512

__device__ __half g_qh[16777216];
__device__ __half g_kh[16777216];
__device__ __half g_vh[16777216];
__device__ __half g_ctxh[16777216];
__device__ __half g_xh[16777216];
__device__ __half g_wth[4 * 1048576];

__device__ __forceinline__ uint32_t smem_u32(const void* p) {
    uint32_t a;
    asm("{ .reg .u64 t; cvta.to.shared.u64 t, %1; cvt.u32.u64 %0, t; }"
        : "=r"(a) : "l"(p));
    return a;
}

__device__ __forceinline__ void mma16816(float* d, const uint32_t* a,
                                         uint32_t b0, uint32_t b1) {
    asm volatile(
        "mma.sync.aligned.m16n8k16.row.col.f32.f16.f16.f32 "
        "{%0,%1,%2,%3}, {%4,%5,%6,%7}, {%8,%9}, {%0,%1,%2,%3};"
        : "+f"(d[0]), "+f"(d[1]), "+f"(d[2]), "+f"(d[3])
        : "r"(a[0]), "r"(a[1]), "r"(a[2]), "r"(a[3]), "r"(b0), "r"(b1));
}

__global__ __launch_bounds__(256) void convert_x_kernel(const float* __restrict__ x)
{
    const int n4 = 16777216 / 4;
    for (int i = blockIdx.x * blockDim.x + threadIdx.x; i < n4;
         i += gridDim.x * blockDim.x) {
        float4 v = ((const float4*)x)[i];
        ((__half2*)g_xh)[i * 2 + 0] = __floats2half2_rn(v.x, v.y);
        ((__half2*)g_xh)[i * 2 + 1] = __floats2half2_rn(v.z, v.w);
    }
}

__global__ __launch_bounds__(256) void transpose_w_kernel(
    const float* __restrict__ src, int which)
{
    __shared__ float t[32][33];
    const int bx = blockIdx.x * 32, by = blockIdx.y * 32;
    const int x = threadIdx.x, y = threadIdx.y;
#pragma unroll
    for (int i = 0; i < 32; i += 8)
        t[y + i][x] = src[(size_t)(by + y + i) * EDIM + bx + x];
    __syncthreads();
    __half* dst = g_wth + (size_t)which * EDIM * EDIM;
#pragma unroll
    for (int i = 0; i < 32; i += 8)
        dst[(size_t)(bx + y + i) * EDIM + by + x] = __float2half_rn(t[x][y + i]);
}

#define LDH 40
#define STAGE_BYTES 20480
#define GEMM_SMEM   67584
#define LDC 132

__global__ __launch_bounds__(256) void gemm_h_kernel(
    const float* __restrict__ bias, float* __restrict__ outp, int mode)
{
    extern __shared__ char sm[];
    __shared__ float bias_s[128];

    const int tid = threadIdx.x, wid = tid >> 5;
    const int warp_m = wid >> 1, warp_n = wid & 1;
    const int m0 = blockIdx.y * 128, n0 = blockIdx.x * 128;

    const __half* Ap = (mode == 3) ? g_ctxh : g_xh;
    const __half* Bp = g_wth + (size_t)mode * (EDIM * EDIM);

    if (tid < 32)
        *(float4*)(bias_s + tid * 4) = *(const float4*)(bias + n0 + tid * 4);

    const uint32_t smb = smem_u32(sm);

    auto load_tile = [&](int t) {
        const int k0 = t * 32;
        const uint32_t Ad = smb + (t % 3) * STAGE_BYTES;
        const uint32_t Bd = Ad + 10240;
#pragma unroll
        for (int i = 0; i < 2; i++) {
            const int c = tid + i * 256;
            const int row = c >> 2, kq = c & 3;
            const __half* ga = Ap + (size_t)(m0 + row) * EDIM + k0 + kq * 8;
            const __half* gb = Bp + (size_t)(n0 + row) * EDIM + k0 + kq * 8;
            const uint32_t da = Ad + row * (LDH * 2) + kq * 16;
            const uint32_t db = Bd + row * (LDH * 2) + kq * 16;
            asm volatile("cp.async.cg.shared.global [%0], [%1], 16;"
                         :: "r"(da), "l"(ga) : "memory");
            asm volatile("cp.async.cg.shared.global [%0], [%1], 16;"
                         :: "r"(db), "l"(gb) : "memory");
        }
        asm volatile("cp.async.commit_group;" ::: "memory");
    };

    wmma::fragment<wmma::accumulator, 16, 16, 16, float> cf[2][4];
#pragma unroll
    for (int i = 0; i < 2; i++)
#pragma unroll
        for (int j = 0; j < 4; j++)
            wmma::fill_fragment(cf[i][j], 0.0f);

    load_tile(0);
    load_tile(1);

    for (int t = 0; t < 32; t++) {
        asm volatile("cp.async.wait_group 1;" ::: "memory");
        __syncthreads();
        if (t + 2 < 32) load_tile(t + 2);

        const __half* As = (const __half*)(sm + (t % 3) * STAGE_BYTES);
        const __half* Bs = As + 10240 / 2;

#pragma unroll
        for (int ks = 0; ks < 2; ks++) {
            const int k16 = ks * 16;
            wmma::fragment<wmma::matrix_a, 16, 16, 16, __half, wmma::row_major> af[2];
            wmma::fragment<wmma::matrix_b, 16, 16, 16, __half, wmma::col_major> bf[4];
#pragma unroll
            for (int i = 0; i < 2; i++)
                wmma::load_matrix_sync(af[i],
                    As + (warp_m * 32 + i * 16) * LDH + k16, LDH);
#pragma unroll
            for (int j = 0; j < 4; j++)
                wmma::load_matrix_sync(bf[j],
                    Bs + (warp_n * 64 + j * 16) * LDH + k16, LDH);
#pragma unroll
            for (int i = 0; i < 2; i++)
#pragma unroll
                for (int j = 0; j < 4; j++)
                    wmma::mma_sync(cf[i][j], af[i], bf[j], cf[i][j]);
        }
    }
    __syncthreads();

    float* Cs = (float*)sm;
#pragma unroll
    for (int i = 0; i < 2; i++)
#pragma unroll
        for (int j = 0; j < 4; j++)
            wmma::store_matrix_sync(
                Cs + (warp_m * 32 + i * 16) * LDC + warp_n * 64 + j * 16,
                cf[i][j], LDC, wmma::mem_row_major);
    __syncthreads();

    const float scale = (mode == 0) ? 0.125f : 1.0f;
    __half* dsth = (mode == 0) ? g_qh : (mode == 1) ? g_kh : g_vh;
#pragma unroll
    for (int i = 0; i < 16; i++) {
        const int e = (tid + i * 256) * 4;
        const int row = e >> 7, col = e & 127;
        const float* c = Cs + row * LDC + col;
        const float* b = bias_s + col;
        float4 v;
        v.x = (c[0] + b[0]) * scale;
        v.y = (c[1] + b[1]) * scale;
        v.z = (c[2] + b[2]) * scale;
        v.w = (c[3] + b[3]) * scale;
        const int m = m0 + row, n = n0 + col;
        if (mode < 3) {
            const int br = m >> 9, cp = m & 511;
            __half2* d2 = (__half2*)(dsth +
                ((size_t)(br * HNUM + (n >> 6)) * CDIM + cp) * DDIM + (n & 63));
            d2[0] = __floats2half2_rn(v.x, v.y);
            d2[1] = __floats2half2_rn(v.z, v.w);
        } else {
            *(float4*)(outp + (size_t)m * EDIM + n) = v;
        }
    }
}

// ---------------------------------------------------------------------------
// Flash attention, raw mma.sync.m16n8k16, register-resident softmax + O.
// ---------------------------------------------------------------------------
#define KVSTR 72
#define AKS0 0
#define AKS1 9216
#define AVT0 18432
#define AVT1 27648
#define ATT_SMEM 36864

__global__ __launch_bounds__(256, 2) void attn_kernel()
{
    extern __shared__ char smc[];
    __half* sh = (__half*)smc;
    const uint32_t smb = smem_u32(smc);

    const int blk = blockIdx.x;
    const int bh = blk >> 2, qb = blk & 3;
    const int t = threadIdx.x;
    const int w = t >> 5, lane = t & 31;
    const int g = lane >> 2, q = lane & 3;

    const __half* qbase = g_qh + (size_t)bh * (CDIM * DDIM) + qb * 128 * DDIM;
    const __half* kbase = g_kh + (size_t)bh * (CDIM * DDIM);
    const __half* vbase = g_vh + (size_t)bh * (CDIM * DDIM);

    uint32_t qa[4][4];
    {
        const __half* qr0 = qbase + (size_t)(w * 16 + g) * 64;
        const __half* qr8 = qr0 + 8 * 64;
#pragma unroll
        for (int s = 0; s < 4; s++) {
            qa[s][0] = *(const uint32_t*)(qr0 + s * 16 + q * 2);
            qa[s][1] = *(const uint32_t*)(qr8 + s * 16 + q * 2);
            qa[s][2] = *(const uint32_t*)(qr0 + s * 16 + 8 + q * 2);
            qa[s][3] = *(const uint32_t*)(qr8 + s * 16 + 8 + q * 2);
        }
    }

    auto load_k = [&](int kb, uint32_t dst) {
#pragma unroll
        for (int i = 0; i < 2; i++) {
            const int c = t + i * 256;
            const int row = c >> 3, ch = c & 7;
            const __half* gk = kbase + (size_t)(kb * 64 + row) * 64 + ch * 8;
            asm volatile("cp.async.cg.shared.global [%0], [%1], 16;"
                :: "r"(smb + dst + (row * KVSTR + ch * 8) * 2), "l"(gk) : "memory");
        }
        asm volatile("cp.async.commit_group;" ::: "memory");
    };
    auto load_v = [&](int kb, int off) {
        const int kr = t & 63, dc = (t >> 6) * 16;
        const __half* gv = vbase + (size_t)(kb * 64 + kr) * 64 + dc;
        uint4 v0 = *(const uint4*)gv;
        uint4 v1 = *(const uint4*)(gv + 8);
        __half h[16];
        *(uint4*)h = v0; *(uint4*)(h + 8) = v1;
        __half* vt = sh + off / 2;
#pragma unroll
        for (int i = 0; i < 16; i++)
            vt[(dc + i) * KVSTR + kr] = h[i];
    };

    float m0 = -1e30f, m1 = -1e30f, l0 = 0.f, l1 = 0.f;
    float O[8][4];
#pragma unroll
    for (int j = 0; j < 8; j++)
#pragma unroll
        for (int r = 0; r < 4; r++) O[j][r] = 0.f;

    load_k(0, AKS0);
    load_v(0, AVT0);

    for (int kb = 0; kb < 8; kb++) {
        const int cur = kb & 1;
        __syncthreads();
        if (kb < 7) {
            load_k(kb + 1, cur ? AKS0 : AKS1);
            load_v(kb + 1, cur ? AVT0 : AVT1);
            asm volatile("cp.async.wait_group 1;" ::: "memory");
        } else {
            asm volatile("cp.async.wait_group 0;" ::: "memory");
        }
        __syncthreads();

        const __half* Ks = sh + (cur ? AKS1 : AKS0) / 2;
        const __half* Vt = sh + (cur ? AVT1 : AVT0) / 2;

        float S[8][4];
#pragma unroll
        for (int j = 0; j < 8; j++) {
#pragma unroll
            for (int r = 0; r < 4; r++) S[j][r] = 0.f;
            const __half* kn = Ks + (j * 8 + g) * KVSTR;
#pragma unroll
            for (int s = 0; s < 4; s++) {
                uint32_t b0 = *(const uint32_t*)(kn + s * 16 + q * 2);
                uint32_t b1 = *(const uint32_t*)(kn + s * 16 + 8 + q * 2);
                mma16816(S[j], qa[s], b0, b1);
            }
        }

        float mx0 = -1e30f, mx1 = -1e30f;
#pragma unroll
        for (int j = 0; j < 8; j++) {
            mx0 = fmaxf(mx0, fmaxf(S[j][0], S[j][1]));
            mx1 = fmaxf(mx1, fmaxf(S[j][2], S[j][3]));
        }
        mx0 = fmaxf(mx0, __shfl_xor_sync(0xffffffffu, mx0, 1));
        mx0 = fmaxf(mx0, __shfl_xor_sync(0xffffffffu, mx0, 2));
        mx1 = fmaxf(mx1, __shfl_xor_sync(0xffffffffu, mx1, 1));
        mx1 = fmaxf(mx1, __shfl_xor_sync(0xffffffffu, mx1, 2));
        const float mn0 = fmaxf(m0, mx0), mn1 = fmaxf(m1, mx1);
        const float corr0 = __expf(m0 - mn0), corr1 = __expf(m1 - mn1);
        m0 = mn0; m1 = mn1;

        float sum0 = 0.f, sum1 = 0.f;
        uint32_t paf[4][4];
#pragma unroll
        for (int s = 0; s < 4; s++) {
#pragma unroll
            for (int jj = 0; jj < 2; jj++) {
                float* Sj = S[2 * s + jj];
                const float p0 = __expf(Sj[0] - mn0);
                const float p1 = __expf(Sj[1] - mn0);
                const float p2 = __expf(Sj[2] - mn1);
                const float p3 = __expf(Sj[3] - mn1);
                sum0 += p0 + p1; sum1 += p2 + p3;
                __half2 h01 = __floats2half2_rn(p0, p1);
                __half2 h23 = __floats2half2_rn(p2, p3);
                paf[s][0 + jj * 2] = *(uint32_t*)&h01;
                paf[s][1 + jj * 2] = *(uint32_t*)&h23;
            }
        }
        sum0 += __shfl_xor_sync(0xffffffffu, sum0, 1);
        sum0 += __shfl_xor_sync(0xffffffffu, sum0, 2);
        sum1 += __shfl_xor_sync(0xffffffffu, sum1, 1);
        sum1 += __shfl_xor_sync(0xffffffffu, sum1, 2);
        l0 = l0 * corr0 + sum0;
        l1 = l1 * corr1 + sum1;

#pragma unroll
        for (int j = 0; j < 8; j++) {
            O[j][0] *= corr0; O[j][1] *= corr0;
            O[j][2] *= corr1; O[j][3] *= corr1;
            const __half* vn = Vt + (j * 8 + g) * KVSTR;
#pragma unroll
            for (int s = 0; s < 4; s++) {
                uint32_t b0 = *(const uint32_t*)(vn + s * 16 + q * 2);
                uint32_t b1 = *(const uint32_t*)(vn + s * 16 + 8 + q * 2);
                mma16816(O[j], paf[s], b0, b1);
            }
        }
    }

    const float i0 = 1.f / l0, i1 = 1.f / l1;
    const int row0 = qb * 128 + w * 16 + g;
    __half* c0 = g_ctxh + ((size_t)(bh >> 4) * CDIM + row0) * EDIM + (bh & 15) * 64;
    __half* c1 = c0 + 8 * EDIM;
#pragma unroll
    for (int j = 0; j < 8; j++) {
        const int col = j * 8 + q * 2;
        *(__half2*)(c0 + col) = __floats2half2_rn(O[j][0] * i0, O[j][1] * i0);
        *(__half2*)(c1 + col) = __floats2half2_rn(O[j][2] * i1, O[j][3] * i1);
    }
}

extern "C" void kernel_launch(void* const* d_in, const int* in_sizes, int n_in,
                              void* d_out, int out_size)
{
    const float* x  = (const float*)d_in[0];
    const float* wq = (const float*)d_in[1];
    const float* bq = (const float*)d_in[2];
    const float* wk = (const float*)d_in[3];
    const float* bk = (const float*)d_in[4];
    const float* wv = (const float*)d_in[5];
    const float* bv = (const float*)d_in[6];
    const float* wo = (const float*)d_in[7];
    const float* bo = (const float*)d_in[8];
    float* out = (float*)d_out;

    convert_x_kernel<<<2048, 256>>>(x);

    dim3 tg(32, 32), tb(32, 8);
    transpose_w_kernel<<<tg, tb>>>(wq, 0);
    transpose_w_kernel<<<tg, tb>>>(wk, 1);
    transpose_w_kernel<<<tg, tb>>>(wv, 2);
    transpose_w_kernel<<<tg, tb>>>(wo, 3);

    cudaFuncSetAttribute(gemm_h_kernel,
                         cudaFuncAttributeMaxDynamicSharedMemorySize, GEMM_SMEM);
    dim3 gg(EDIM / 128, MTOT / 128);
    gemm_h_kernel<<<gg, 256, GEMM_SMEM>>>(bq, nullptr, 0);
    gemm_h_kernel<<<gg, 256, GEMM_SMEM>>>(bk, nullptr, 1);
    gemm_h_kernel<<<gg, 256, GEMM_SMEM>>>(bv, nullptr, 2);

    cudaFuncSetAttribute(attn_kernel,
                         cudaFuncAttributeMaxDynamicSharedMemorySize, ATT_SMEM);
    attn_kernel<<<NBH * 4, 256, ATT_SMEM>>>();

    gemm_h_kernel<<<gg, 256, GEMM_SMEM>>>(bo, out, 3);
}